// round 2
// baseline (speedup 1.0000x reference)
#include <cuda_runtime.h>

#define BB 32
#define TT 2048
#define CCH 384
#define HH 64
#define LDSP 68   // 64 + 4 float pad per row (keeps 16B alignment, breaks bank conflicts)

// Scratch for projected q,k,v: [B][T][H] fp32, 16 MB each (static device arrays — no allocs)
__device__ float g_q[BB * TT * HH];
__device__ float g_k[BB * TT * HH];
__device__ float g_v[BB * TT * HH];

// ---------------------------------------------------------------------------
// Kernel 1: fused QKV projection.  out[b,t,h] = sum_c x[b,t,c] * W[c,h] for 3 Ws.
// Block = 64 rows (t) x 64 cols (h), 256 threads, 4x4 register micro-tile per
// thread per matrix. C reduced in chunks of 32 staged through SMEM; each x tile
// is reused by all three weight matrices.
// ---------------------------------------------------------------------------
__global__ __launch_bounds__(256) void qkv_proj(
    const float* __restrict__ x,
    const float* __restrict__ Wk,
    const float* __restrict__ Wq,
    const float* __restrict__ Wv)
{
    __shared__ float xs[64][36];        // 64 rows x 32 c (+4 pad)
    __shared__ float wks[32][LDSP];
    __shared__ float wqs[32][LDSP];
    __shared__ float wvs[32][LDSP];

    const int b   = blockIdx.y;
    const int r0  = blockIdx.x * 64;
    const int tid = threadIdx.x;
    const int ty  = tid >> 4, tx = tid & 15;
    const int i0  = ty * 4,  j0 = tx * 4;

    float aK[4][4] = {};
    float aQ[4][4] = {};
    float aV[4][4] = {};

    const float* xb = x + ((size_t)b * TT + r0) * CCH;

    for (int c0 = 0; c0 < CCH; c0 += 32) {
        __syncthreads();
        // stage x tile: 64 rows x 32 cols
        {
            int row = tid >> 3;
            int col = (tid & 7) << 2;
            #pragma unroll
            for (int p = 0; p < 2; p++) {
                float4 v = *reinterpret_cast<const float4*>(
                    xb + (size_t)(row + 32 * p) * CCH + c0 + col);
                *reinterpret_cast<float4*>(&xs[row + 32 * p][col]) = v;
            }
        }
        // stage weights: 32 c x 64 h, all three matrices
        {
            int row = tid >> 4;
            int col = (tid & 15) << 2;
            #pragma unroll
            for (int p = 0; p < 2; p++) {
                int rr = row + 16 * p;
                size_t g = (size_t)(c0 + rr) * HH + col;
                *reinterpret_cast<float4*>(&wks[rr][col]) = *reinterpret_cast<const float4*>(Wk + g);
                *reinterpret_cast<float4*>(&wqs[rr][col]) = *reinterpret_cast<const float4*>(Wq + g);
                *reinterpret_cast<float4*>(&wvs[rr][col]) = *reinterpret_cast<const float4*>(Wv + g);
            }
        }
        __syncthreads();

        #pragma unroll
        for (int cc = 0; cc < 32; cc += 4) {
            float ax[4][4];
            #pragma unroll
            for (int r = 0; r < 4; r++) {
                float4 t = *reinterpret_cast<const float4*>(&xs[i0 + r][cc]);
                ax[r][0] = t.x; ax[r][1] = t.y; ax[r][2] = t.z; ax[r][3] = t.w;
            }
            #pragma unroll
            for (int c = 0; c < 4; c++) {
                float4 wk4 = *reinterpret_cast<const float4*>(&wks[cc + c][j0]);
                float4 wq4 = *reinterpret_cast<const float4*>(&wqs[cc + c][j0]);
                float4 wv4 = *reinterpret_cast<const float4*>(&wvs[cc + c][j0]);
                #pragma unroll
                for (int r = 0; r < 4; r++) {
                    float a = ax[r][c];
                    aK[r][0] += a * wk4.x; aK[r][1] += a * wk4.y;
                    aK[r][2] += a * wk4.z; aK[r][3] += a * wk4.w;
                    aQ[r][0] += a * wq4.x; aQ[r][1] += a * wq4.y;
                    aQ[r][2] += a * wq4.z; aQ[r][3] += a * wq4.w;
                    aV[r][0] += a * wv4.x; aV[r][1] += a * wv4.y;
                    aV[r][2] += a * wv4.z; aV[r][3] += a * wv4.w;
                }
            }
        }
    }

    #pragma unroll
    for (int r = 0; r < 4; r++) {
        size_t o = ((size_t)b * TT + r0 + i0 + r) * HH + j0;
        *reinterpret_cast<float4*>(&g_k[o]) = make_float4(aK[r][0], aK[r][1], aK[r][2], aK[r][3]);
        *reinterpret_cast<float4*>(&g_q[o]) = make_float4(aQ[r][0], aQ[r][1], aQ[r][2], aQ[r][3]);
        *reinterpret_cast<float4*>(&g_v[o]) = make_float4(aV[r][0], aV[r][1], aV[r][2], aV[r][3]);
    }
}

// ---------------------------------------------------------------------------
// Kernel 2: causal flash attention. One block per (q-tile of 64, batch).
// Online softmax with per-thread replicated row stats; 4x4 micro-tiles for
// both S = Q K^T and O += P V; V kept transposed in SMEM so the PV reduction
// vectorizes with float4.
// ---------------------------------------------------------------------------
__global__ __launch_bounds__(256) void attn_kernel(float* __restrict__ out)
{
    extern __shared__ float smem[];
    float* Qs = smem;                 // [64][LDSP]
    float* Ks = Qs + 64 * LDSP;       // [64][LDSP]
    float* Vt = Ks + 64 * LDSP;       // [64][LDSP]  (transposed: Vt[h][s])
    float* Ps = Vt + 64 * LDSP;       // [64][LDSP]

    const int b   = blockIdx.y;
    const int qt  = blockIdx.x;
    const int q0  = qt * 64;
    const int tid = threadIdx.x;
    const int ty  = tid >> 4, tx = tid & 15;
    const int i0  = ty * 4,  j0 = tx * 4;

    // load Q tile
    {
        const float* qb = g_q + ((size_t)b * TT + q0) * HH;
        int row = tid >> 4;
        int col = (tid & 15) << 2;
        #pragma unroll
        for (int p = 0; p < 4; p++) {
            int rr = row + 16 * p;
            float4 v = *reinterpret_cast<const float4*>(qb + (size_t)rr * HH + col);
            *reinterpret_cast<float4*>(&Qs[rr * LDSP + col]) = v;
        }
    }

    float m_r[4], l_r[4], acc[4][4];
    #pragma unroll
    for (int r = 0; r < 4; r++) {
        m_r[r] = -1e30f; l_r[r] = 0.f;
        #pragma unroll
        for (int c = 0; c < 4; c++) acc[r][c] = 0.f;
    }
    __syncthreads();

    const float scale = 0.125f;   // H^-0.5 = 1/8

    for (int kt = 0; kt <= qt; kt++) {
        // stage K tile + transposed V tile
        {
            const float* kb = g_k + ((size_t)b * TT + kt * 64) * HH;
            const float* vb = g_v + ((size_t)b * TT + kt * 64) * HH;
            int row = tid >> 4;
            int col = (tid & 15) << 2;
            #pragma unroll
            for (int p = 0; p < 4; p++) {
                int rr = row + 16 * p;
                float4 kv = *reinterpret_cast<const float4*>(kb + (size_t)rr * HH + col);
                *reinterpret_cast<float4*>(&Ks[rr * LDSP + col]) = kv;
                float4 vv = *reinterpret_cast<const float4*>(vb + (size_t)rr * HH + col);
                Vt[(col + 0) * LDSP + rr] = vv.x;
                Vt[(col + 1) * LDSP + rr] = vv.y;
                Vt[(col + 2) * LDSP + rr] = vv.z;
                Vt[(col + 3) * LDSP + rr] = vv.w;
            }
        }
        __syncthreads();

        // S = Q K^T
        float s[4][4] = {};
        #pragma unroll
        for (int hc = 0; hc < 64; hc += 4) {
            float aq[4][4], ak[4][4];
            #pragma unroll
            for (int r = 0; r < 4; r++) {
                float4 t = *reinterpret_cast<const float4*>(&Qs[(i0 + r) * LDSP + hc]);
                aq[r][0] = t.x; aq[r][1] = t.y; aq[r][2] = t.z; aq[r][3] = t.w;
            }
            #pragma unroll
            for (int c = 0; c < 4; c++) {
                float4 t = *reinterpret_cast<const float4*>(&Ks[(j0 + c) * LDSP + hc]);
                ak[c][0] = t.x; ak[c][1] = t.y; ak[c][2] = t.z; ak[c][3] = t.w;
            }
            #pragma unroll
            for (int r = 0; r < 4; r++)
                #pragma unroll
                for (int c = 0; c < 4; c++)
                    #pragma unroll
                    for (int h = 0; h < 4; h++)
                        s[r][c] += aq[r][h] * ak[c][h];
        }

        // scale + causal mask (only diagonal tile needs masking)
        if (kt == qt) {
            #pragma unroll
            for (int r = 0; r < 4; r++)
                #pragma unroll
                for (int c = 0; c < 4; c++)
                    s[r][c] = (j0 + c > i0 + r) ? -1e30f : s[r][c] * scale;
        } else {
            #pragma unroll
            for (int r = 0; r < 4; r++)
                #pragma unroll
                for (int c = 0; c < 4; c++)
                    s[r][c] *= scale;
        }

        // row max across the 16 threads sharing a row group (tx dimension)
        float rmax[4];
        #pragma unroll
        for (int r = 0; r < 4; r++) {
            rmax[r] = fmaxf(fmaxf(s[r][0], s[r][1]), fmaxf(s[r][2], s[r][3]));
            #pragma unroll
            for (int off = 1; off < 16; off <<= 1)
                rmax[r] = fmaxf(rmax[r], __shfl_xor_sync(0xffffffffu, rmax[r], off));
        }

        float fac[4], rsum[4];
        #pragma unroll
        for (int r = 0; r < 4; r++) {
            float mnew = fmaxf(m_r[r], rmax[r]);
            fac[r] = __expf(m_r[r] - mnew);
            m_r[r] = mnew;
            rsum[r] = 0.f;
            #pragma unroll
            for (int c = 0; c < 4; c++) {
                float p = __expf(s[r][c] - mnew);
                s[r][c] = p;
                rsum[r] += p;
            }
            #pragma unroll
            for (int off = 1; off < 16; off <<= 1)
                rsum[r] += __shfl_xor_sync(0xffffffffu, rsum[r], off);
            l_r[r] = l_r[r] * fac[r] + rsum[r];
            #pragma unroll
            for (int c = 0; c < 4; c++) acc[r][c] *= fac[r];
        }

        // publish P
        #pragma unroll
        for (int r = 0; r < 4; r++)
            *reinterpret_cast<float4*>(&Ps[(i0 + r) * LDSP + j0]) =
                make_float4(s[r][0], s[r][1], s[r][2], s[r][3]);
        __syncthreads();

        // O += P @ V   (Vt[h][s] -> float4 along s)
        #pragma unroll
        for (int sc = 0; sc < 64; sc += 4) {
            float ap[4][4], av[4][4];
            #pragma unroll
            for (int r = 0; r < 4; r++) {
                float4 t = *reinterpret_cast<const float4*>(&Ps[(i0 + r) * LDSP + sc]);
                ap[r][0] = t.x; ap[r][1] = t.y; ap[r][2] = t.z; ap[r][3] = t.w;
            }
            #pragma unroll
            for (int c = 0; c < 4; c++) {
                float4 t = *reinterpret_cast<const float4*>(&Vt[(j0 + c) * LDSP + sc]);
                av[c][0] = t.x; av[c][1] = t.y; av[c][2] = t.z; av[c][3] = t.w;
            }
            #pragma unroll
            for (int r = 0; r < 4; r++)
                #pragma unroll
                for (int c = 0; c < 4; c++)
                    #pragma unroll
                    for (int k = 0; k < 4; k++)
                        acc[r][c] += ap[r][k] * av[c][k];
        }
        __syncthreads();
    }

    // finalize and store
    float* ob = out + ((size_t)b * TT + q0) * HH;
    #pragma unroll
    for (int r = 0; r < 4; r++) {
        float inv = 1.0f / l_r[r];
        *reinterpret_cast<float4*>(&ob[(size_t)(i0 + r) * HH + j0]) =
            make_float4(acc[r][0] * inv, acc[r][1] * inv, acc[r][2] * inv, acc[r][3] * inv);
    }
}

extern "C" void kernel_launch(void* const* d_in, const int* in_sizes, int n_in,
                              void* d_out, int out_size)
{
    const float* x  = (const float*)d_in[0];
    const float* Wk = (const float*)d_in[1];
    const float* Wq = (const float*)d_in[2];
    const float* Wv = (const float*)d_in[3];
    float* out = (float*)d_out;

    (void)in_sizes; (void)n_in; (void)out_size;

    dim3 gridP(TT / 64, BB);
    qkv_proj<<<gridP, 256>>>(x, Wk, Wq, Wv);

    static int smem_set = 0;
    const int smem_bytes = 4 * 64 * LDSP * sizeof(float);  // 69632 B
    if (!smem_set) {
        cudaFuncSetAttribute(attn_kernel, cudaFuncAttributeMaxDynamicSharedMemorySize, smem_bytes);
        smem_set = 1;
    }
    dim3 gridA(TT / 64, BB);
    attn_kernel<<<gridA, 256, smem_bytes>>>(out);
}

// round 6
// speedup vs baseline: 3.6799x; 3.6799x over previous
#include <cuda_runtime.h>
#include <cuda_bf16.h>
#include <cstdint>

#define BB 32
#define TT 2048
#define CCH 384
#define HH 64

typedef unsigned int u32;
typedef unsigned short u16;

// ---------------- global split-bf16 buffers (static: no allocs) -------------
__device__ __align__(16) u16 g_x_hi[BB * TT * CCH];
__device__ __align__(16) u16 g_x_lo[BB * TT * CCH];
__device__ __align__(16) u16 g_wt_hi[3 * HH * CCH];   // [w][n][k] transposed
__device__ __align__(16) u16 g_wt_lo[3 * HH * CCH];
__device__ __align__(16) u16 g_q_hi[BB * TT * HH];    // q pre-scaled by 1/8
__device__ __align__(16) u16 g_q_lo[BB * TT * HH];
__device__ __align__(16) u16 g_k_hi[BB * TT * HH];
__device__ __align__(16) u16 g_k_lo[BB * TT * HH];
__device__ __align__(16) u16 g_v_hi[BB * TT * HH];
__device__ __align__(16) u16 g_v_lo[BB * TT * HH];

// ---------------- helpers ---------------------------------------------------
static __device__ __forceinline__ u32 smem_u32(const void* p) {
    u32 a;
    asm("{ .reg .u64 t; cvta.to.shared.u64 t, %1; cvt.u32.u64 %0, t; }" : "=r"(a) : "l"(p));
    return a;
}
static __device__ __forceinline__ void ldsm_x4(u32 r[4], u32 a) {
    asm volatile("ldmatrix.sync.aligned.m8n8.x4.shared.b16 {%0,%1,%2,%3}, [%4];"
                 : "=r"(r[0]), "=r"(r[1]), "=r"(r[2]), "=r"(r[3]) : "r"(a));
}
static __device__ __forceinline__ void ldsm_x2(u32 r[2], u32 a) {
    asm volatile("ldmatrix.sync.aligned.m8n8.x2.shared.b16 {%0,%1}, [%2];"
                 : "=r"(r[0]), "=r"(r[1]) : "r"(a));
}
static __device__ __forceinline__ void ldsm_x2t(u32 r[2], u32 a) {
    asm volatile("ldmatrix.sync.aligned.m8n8.x2.trans.shared.b16 {%0,%1}, [%2];"
                 : "=r"(r[0]), "=r"(r[1]) : "r"(a));
}
static __device__ __forceinline__ void mma_bf16(float d[4], const u32 a[4], const u32 b[2]) {
    asm volatile("mma.sync.aligned.m16n8k16.row.col.f32.bf16.bf16.f32 "
                 "{%0,%1,%2,%3}, {%4,%5,%6,%7}, {%8,%9}, {%0,%1,%2,%3};"
                 : "+f"(d[0]), "+f"(d[1]), "+f"(d[2]), "+f"(d[3])
                 : "r"(a[0]), "r"(a[1]), "r"(a[2]), "r"(a[3]), "r"(b[0]), "r"(b[1]));
}
static __device__ __forceinline__ u32 packbf2(float a, float b) {
    __nv_bfloat162 v;
    v.x = __float2bfloat16(a);
    v.y = __float2bfloat16(b);
    return *reinterpret_cast<u32*>(&v);
}
static __device__ __forceinline__ void split2(float a, float b, u32& hi, u32& lo) {
    float ha = __bfloat162float(__float2bfloat16(a));
    float hb = __bfloat162float(__float2bfloat16(b));
    hi = packbf2(ha, hb);
    lo = packbf2(a - ha, b - hb);
}

// ---------------- prepass: split x ------------------------------------------
__global__ __launch_bounds__(256) void split_x(const float* __restrict__ x) {
    size_t i = ((size_t)blockIdx.x * blockDim.x + threadIdx.x) * 4;
    float4 v = *reinterpret_cast<const float4*>(x + i);
    u32 h0, l0, h1, l1;
    split2(v.x, v.y, h0, l0);
    split2(v.z, v.w, h1, l1);
    *reinterpret_cast<uint2*>(g_x_hi + i) = make_uint2(h0, h1);
    *reinterpret_cast<uint2*>(g_x_lo + i) = make_uint2(l0, l1);
}

// ---------------- prepass: split + transpose weights ------------------------
__global__ __launch_bounds__(256) void split_w(const float* __restrict__ Wk,
                                               const float* __restrict__ Wq,
                                               const float* __restrict__ Wv) {
    int id = blockIdx.x * blockDim.x + threadIdx.x;   // < 3*64*384
    int w = id / (HH * CCH);
    int r = id % (HH * CCH);
    int n = r / CCH;
    int k = r % CCH;
    const float* W = (w == 0) ? Wk : (w == 1) ? Wq : Wv;
    float v = W[k * HH + n];
    float h = __bfloat162float(__float2bfloat16(v));
    __nv_bfloat16 bh = __float2bfloat16(h);
    __nv_bfloat16 bl = __float2bfloat16(v - h);
    g_wt_hi[id] = *reinterpret_cast<u16*>(&bh);
    g_wt_lo[id] = *reinterpret_cast<u16*>(&bl);
}

// ---------------- projection: out = x @ W via HMMA, split-bf16 --------------
#define XPAD 40   // smem row stride in elems (80B) for k-chunk-32 tiles

__global__ __launch_bounds__(128) void proj_mma() {
    __shared__ u16 xs_hi[128 * XPAD], xs_lo[128 * XPAD];
    __shared__ u16 ws_hi[64 * XPAD],  ws_lo[64 * XPAD];

    const int tid  = threadIdx.x;
    const int lane = tid & 31;
    const int wp   = tid >> 5;
    const int l16  = lane & 15;
    const int m0   = blockIdx.x * 128;
    const int b    = blockIdx.y;
    const int w    = blockIdx.z;

    const u32 xhb = smem_u32(xs_hi), xlb = smem_u32(xs_lo);
    const u32 whb = smem_u32(ws_hi), wlb = smem_u32(ws_lo);

    float acc[2][8][4];
    #pragma unroll
    for (int mt = 0; mt < 2; mt++)
        #pragma unroll
        for (int n = 0; n < 8; n++)
            #pragma unroll
            for (int j = 0; j < 4; j++) acc[mt][n][j] = 0.f;

    const size_t xrow0 = (size_t)b * TT + m0;

    for (int c0 = 0; c0 < CCH; c0 += 32) {
        __syncthreads();
        // stage x chunk: 128 rows x 32 k
        {
            const uint4* sh = reinterpret_cast<const uint4*>(g_x_hi + (xrow0 + tid) * CCH + c0);
            const uint4* sl = reinterpret_cast<const uint4*>(g_x_lo + (xrow0 + tid) * CCH + c0);
            uint4* dh = reinterpret_cast<uint4*>(xs_hi + tid * XPAD);
            uint4* dl = reinterpret_cast<uint4*>(xs_lo + tid * XPAD);
            #pragma unroll
            for (int i = 0; i < 4; i++) { dh[i] = sh[i]; dl[i] = sl[i]; }
        }
        // stage W^T chunk: 64 n-rows x 32 k
        {
            int rr = tid >> 1, ko = (tid & 1) * 16;
            const uint4* sh = reinterpret_cast<const uint4*>(g_wt_hi + ((size_t)w * HH + rr) * CCH + c0 + ko);
            const uint4* sl = reinterpret_cast<const uint4*>(g_wt_lo + ((size_t)w * HH + rr) * CCH + c0 + ko);
            uint4* dh = reinterpret_cast<uint4*>(ws_hi + rr * XPAD + ko);
            uint4* dl = reinterpret_cast<uint4*>(ws_lo + rr * XPAD + ko);
            #pragma unroll
            for (int i = 0; i < 2; i++) { dh[i] = sh[i]; dl[i] = sl[i]; }
        }
        __syncthreads();

        #pragma unroll
        for (int ks = 0; ks < 2; ks++) {
            u32 ah[2][4], al[2][4];
            #pragma unroll
            for (int mt = 0; mt < 2; mt++) {
                int row = wp * 32 + mt * 16 + (lane & 7) + ((lane >> 3) & 1) * 8;
                u32 off = row * (XPAD * 2) + ks * 32 + (lane >> 4) * 16;
                ldsm_x4(ah[mt], xhb + off);
                ldsm_x4(al[mt], xlb + off);
            }
            #pragma unroll
            for (int n = 0; n < 8; n++) {
                u32 boff = (n * 8 + (l16 & 7)) * (XPAD * 2) + ks * 32 + (l16 >> 3) * 16;
                u32 bh[2], bl[2];
                ldsm_x2(bh, whb + boff);
                ldsm_x2(bl, wlb + boff);
                #pragma unroll
                for (int mt = 0; mt < 2; mt++) {
                    mma_bf16(acc[mt][n], ah[mt], bh);
                    mma_bf16(acc[mt][n], ah[mt], bl);
                    mma_bf16(acc[mt][n], al[mt], bh);
                }
            }
        }
    }

    // epilogue: split accum to bf16 hi/lo, write to q/k/v buffers
    u16 *dh, *dl;
    float scale = 1.f;
    if (w == 0)      { dh = g_k_hi; dl = g_k_lo; }
    else if (w == 1) { dh = g_q_hi; dl = g_q_lo; scale = 0.125f; }
    else             { dh = g_v_hi; dl = g_v_lo; }

    #pragma unroll
    for (int mt = 0; mt < 2; mt++) {
        #pragma unroll
        for (int n = 0; n < 8; n++) {
            int col = n * 8 + (lane & 3) * 2;
            #pragma unroll
            for (int half = 0; half < 2; half++) {
                int row = m0 + wp * 32 + mt * 16 + (lane >> 2) + half * 8;
                float v0 = acc[mt][n][half * 2]     * scale;
                float v1 = acc[mt][n][half * 2 + 1] * scale;
                u32 hi, lo;
                split2(v0, v1, hi, lo);
                size_t o = ((size_t)b * TT + row) * HH + col;
                *reinterpret_cast<u32*>(dh + o) = hi;
                *reinterpret_cast<u32*>(dl + o) = lo;
            }
        }
    }
}

// ---------------- attention: FA2 with HMMA, split-bf16 ----------------------
#define APAD 72   // smem row stride in elems (144B) for 64-col tiles

static __device__ __forceinline__ void stage64(u16* dst, const u16* __restrict__ src, int tid) {
    int row = tid >> 1, half = tid & 1;
    const uint4* s = reinterpret_cast<const uint4*>(src + (size_t)row * HH + half * 32);
    uint4* d = reinterpret_cast<uint4*>(dst + row * APAD + half * 32);
    #pragma unroll
    for (int i = 0; i < 4; i++) d[i] = s[i];
}

__global__ __launch_bounds__(128) void attn_mma(float* __restrict__ out) {
    __shared__ u16 Kh[64 * APAD], Kl[64 * APAD], Vh[64 * APAD], Vl[64 * APAD];

    const int tid  = threadIdx.x;
    const int lane = tid & 31;
    const int wp   = tid >> 5;
    const int l16  = lane & 15;
    const int b    = blockIdx.y;
    const int qt   = blockIdx.x;
    const int q0   = qt * 64;

    const u32 khb = smem_u32(Kh), klb = smem_u32(Kl);
    const u32 vhb = smem_u32(Vh), vlb = smem_u32(Vl);

    // ---- prologue: stage Q (reusing K buffers), load Q fragments to regs ----
    stage64(Kh, g_q_hi + ((size_t)b * TT + q0) * HH, tid);
    stage64(Kl, g_q_lo + ((size_t)b * TT + q0) * HH, tid);
    __syncthreads();

    u32 qa_h[4][4], qa_l[4][4];
    {
        int arow = wp * 16 + (lane & 7) + ((lane >> 3) & 1) * 8;
        #pragma unroll
        for (int ks = 0; ks < 4; ks++) {
            u32 off = arow * (APAD * 2) + ks * 32 + (lane >> 4) * 16;
            ldsm_x4(qa_h[ks], khb + off);
            ldsm_x4(qa_l[ks], klb + off);
        }
    }

    float Oacc[8][4];
    #pragma unroll
    for (int n = 0; n < 8; n++)
        #pragma unroll
        for (int j = 0; j < 4; j++) Oacc[n][j] = 0.f;

    float mrow[2] = { -1e30f, -1e30f };
    float lrow[2] = { 0.f, 0.f };
    const int qrow0 = q0 + wp * 16 + (lane >> 2);   // this thread's first q-row

    for (int kt = 0; kt <= qt; kt++) {
        const int k0 = kt * 64;
        __syncthreads();
        stage64(Kh, g_k_hi + ((size_t)b * TT + k0) * HH, tid);
        stage64(Kl, g_k_lo + ((size_t)b * TT + k0) * HH, tid);
        stage64(Vh, g_v_hi + ((size_t)b * TT + k0) * HH, tid);
        stage64(Vl, g_v_lo + ((size_t)b * TT + k0) * HH, tid);
        __syncthreads();

        // ---- S = Q K^T (3-term split) ----
        float S[8][4];
        #pragma unroll
        for (int n = 0; n < 8; n++)
            #pragma unroll
            for (int j = 0; j < 4; j++) S[n][j] = 0.f;

        #pragma unroll
        for (int n = 0; n < 8; n++) {
            #pragma unroll
            for (int ks = 0; ks < 4; ks++) {
                u32 boff = (n * 8 + (l16 & 7)) * (APAD * 2) + ks * 32 + (l16 >> 3) * 16;
                u32 bh[2], bl[2];
                ldsm_x2(bh, khb + boff);
                ldsm_x2(bl, klb + boff);
                mma_bf16(S[n], qa_h[ks], bh);
                mma_bf16(S[n], qa_h[ks], bl);
                mma_bf16(S[n], qa_l[ks], bh);
            }
        }

        // ---- causal mask (diagonal tile only) ----
        if (kt == qt) {
            #pragma unroll
            for (int n = 0; n < 8; n++) {
                int colb = k0 + n * 8 + (lane & 3) * 2;
                #pragma unroll
                for (int j = 0; j < 4; j++) {
                    int col = colb + (j & 1);
                    int row = qrow0 + (j >> 1) * 8;
                    if (col > row) S[n][j] = -1e30f;
                }
            }
        }

        // ---- online softmax ----
        float fac[2];
        #pragma unroll
        for (int h = 0; h < 2; h++) {
            float mx = -1e30f;
            #pragma unroll
            for (int n = 0; n < 8; n++)
                mx = fmaxf(mx, fmaxf(S[n][h * 2], S[n][h * 2 + 1]));
            mx = fmaxf(mx, __shfl_xor_sync(0xffffffffu, mx, 1));
            mx = fmaxf(mx, __shfl_xor_sync(0xffffffffu, mx, 2));
            float mnew = fmaxf(mrow[h], mx);
            fac[h] = __expf(mrow[h] - mnew);
            mrow[h] = mnew;
            float sum = 0.f;
            #pragma unroll
            for (int n = 0; n < 8; n++) {
                float p0 = __expf(S[n][h * 2]     - mnew);
                float p1 = __expf(S[n][h * 2 + 1] - mnew);
                S[n][h * 2] = p0;
                S[n][h * 2 + 1] = p1;
                sum += p0 + p1;
            }
            sum += __shfl_xor_sync(0xffffffffu, sum, 1);
            sum += __shfl_xor_sync(0xffffffffu, sum, 2);
            lrow[h] = lrow[h] * fac[h] + sum;
            #pragma unroll
            for (int n = 0; n < 8; n++) {
                Oacc[n][h * 2]     *= fac[h];
                Oacc[n][h * 2 + 1] *= fac[h];
            }
        }

        // ---- O += P V (P packed reg->reg from S; 3-term split) ----
        #pragma unroll
        for (int ks = 0; ks < 4; ks++) {
            u32 pa_h[4], pa_l[4];
            #pragma unroll
            for (int j = 0; j < 4; j++) {
                int n = 2 * ks + (j >> 1);
                int base = (j & 1) * 2;
                split2(S[n][base], S[n][base + 1], pa_h[j], pa_l[j]);
            }
            #pragma unroll
            for (int n = 0; n < 8; n++) {
                u32 voff = (ks * 16 + l16) * (APAD * 2) + n * 16;
                u32 bh[2], bl[2];
                ldsm_x2t(bh, vhb + voff);
                ldsm_x2t(bl, vlb + voff);
                mma_bf16(Oacc[n], pa_h, bh);
                mma_bf16(Oacc[n], pa_h, bl);
                mma_bf16(Oacc[n], pa_l, bh);
            }
        }
    }

    // ---- finalize ----
    float inv0 = 1.f / lrow[0];
    float inv1 = 1.f / lrow[1];
    #pragma unroll
    for (int n = 0; n < 8; n++) {
        int col = n * 8 + (lane & 3) * 2;
        int row0 = q0 + wp * 16 + (lane >> 2);
        float2 v0 = make_float2(Oacc[n][0] * inv0, Oacc[n][1] * inv0);
        float2 v1 = make_float2(Oacc[n][2] * inv1, Oacc[n][3] * inv1);
        *reinterpret_cast<float2*>(out + ((size_t)b * TT + row0) * HH + col) = v0;
        *reinterpret_cast<float2*>(out + ((size_t)b * TT + row0 + 8) * HH + col) = v1;
    }
}

// ---------------------------------------------------------------------------
extern "C" void kernel_launch(void* const* d_in, const int* in_sizes, int n_in,
                              void* d_out, int out_size)
{
    const float* x  = (const float*)d_in[0];
    const float* Wk = (const float*)d_in[1];
    const float* Wq = (const float*)d_in[2];
    const float* Wv = (const float*)d_in[3];
    float* out = (float*)d_out;
    (void)in_sizes; (void)n_in; (void)out_size;

    split_x<<<(BB * TT * CCH) / (4 * 256), 256>>>(x);
    split_w<<<(3 * HH * CCH) / 256, 256>>>(Wk, Wq, Wv);

    dim3 gridP(TT / 128, BB, 3);
    proj_mma<<<gridP, 128>>>();

    dim3 gridA(TT / 64, BB);
    attn_mma<<<gridA, 128>>>(out);
}

// round 9
// speedup vs baseline: 4.3965x; 1.1947x over previous
#include <cuda_runtime.h>
#include <cuda_bf16.h>
#include <cstdint>

#define BB 32
#define TT 2048
#define CCH 384
#define HH 64

typedef unsigned int u32;
typedef unsigned short u16;

// ---------------- global split-bf16 buffers (static: no allocs) -------------
__device__ __align__(16) u16 g_wt_hi[3 * HH * CCH];   // [w][n][k] transposed
__device__ __align__(16) u16 g_wt_lo[3 * HH * CCH];
__device__ __align__(16) u16 g_q_hi[BB * TT * HH];    // q pre-scaled by 1/8
__device__ __align__(16) u16 g_q_lo[BB * TT * HH];
__device__ __align__(16) u16 g_k_hi[BB * TT * HH];
__device__ __align__(16) u16 g_k_lo[BB * TT * HH];
__device__ __align__(16) u16 g_v_hi[BB * TT * HH];
__device__ __align__(16) u16 g_v_lo[BB * TT * HH];

// ---------------- helpers ---------------------------------------------------
static __device__ __forceinline__ u32 smem_u32(const void* p) {
    u32 a;
    asm("{ .reg .u64 t; cvta.to.shared.u64 t, %1; cvt.u32.u64 %0, t; }" : "=r"(a) : "l"(p));
    return a;
}
static __device__ __forceinline__ void ldsm_x4(u32 r[4], u32 a) {
    asm volatile("ldmatrix.sync.aligned.m8n8.x4.shared.b16 {%0,%1,%2,%3}, [%4];"
                 : "=r"(r[0]), "=r"(r[1]), "=r"(r[2]), "=r"(r[3]) : "r"(a));
}
static __device__ __forceinline__ void ldsm_x2(u32 r[2], u32 a) {
    asm volatile("ldmatrix.sync.aligned.m8n8.x2.shared.b16 {%0,%1}, [%2];"
                 : "=r"(r[0]), "=r"(r[1]) : "r"(a));
}
static __device__ __forceinline__ void ldsm_x2t(u32 r[2], u32 a) {
    asm volatile("ldmatrix.sync.aligned.m8n8.x2.trans.shared.b16 {%0,%1}, [%2];"
                 : "=r"(r[0]), "=r"(r[1]) : "r"(a));
}
static __device__ __forceinline__ void mma_bf16(float d[4], const u32 a[4], const u32 b[2]) {
    asm volatile("mma.sync.aligned.m16n8k16.row.col.f32.bf16.bf16.f32 "
                 "{%0,%1,%2,%3}, {%4,%5,%6,%7}, {%8,%9}, {%0,%1,%2,%3};"
                 : "+f"(d[0]), "+f"(d[1]), "+f"(d[2]), "+f"(d[3])
                 : "r"(a[0]), "r"(a[1]), "r"(a[2]), "r"(a[3]), "r"(b[0]), "r"(b[1]));
}
static __device__ __forceinline__ u32 packbf2(float a, float b) {
    __nv_bfloat162 v;
    v.x = __float2bfloat16(a);
    v.y = __float2bfloat16(b);
    return *reinterpret_cast<u32*>(&v);
}
static __device__ __forceinline__ void split2(float a, float b, u32& hi, u32& lo) {
    float ha = __bfloat162float(__float2bfloat16(a));
    float hb = __bfloat162float(__float2bfloat16(b));
    hi = packbf2(ha, hb);
    lo = packbf2(a - ha, b - hb);
}
static __device__ __forceinline__ void cpa16(u32 dst, const void* src) {
    asm volatile("cp.async.cg.shared.global [%0], [%1], 16;" :: "r"(dst), "l"(src));
}
#define CP_COMMIT() asm volatile("cp.async.commit_group;" ::: "memory")
#define CP_WAIT1()  asm volatile("cp.async.wait_group 1;" ::: "memory")
#define CP_WAIT0()  asm volatile("cp.async.wait_group 0;" ::: "memory")

// ---------------- prepass: split + transpose weights ------------------------
__global__ __launch_bounds__(256) void split_w(const float* __restrict__ Wk,
                                               const float* __restrict__ Wq,
                                               const float* __restrict__ Wv) {
    int id = blockIdx.x * blockDim.x + threadIdx.x;   // < 3*64*384
    int w = id / (HH * CCH);
    int r = id % (HH * CCH);
    int n = r / CCH;
    int k = r % CCH;
    const float* W = (w == 0) ? Wk : (w == 1) ? Wq : Wv;
    float v = W[k * HH + n];
    float h = __bfloat162float(__float2bfloat16(v));
    __nv_bfloat16 bh = __float2bfloat16(h);
    __nv_bfloat16 bl = __float2bfloat16(v - h);
    g_wt_hi[id] = *reinterpret_cast<u16*>(&bh);
    g_wt_lo[id] = *reinterpret_cast<u16*>(&bl);
}

// ---------------- projection: q/k/v = x @ W, fused 3 weights ----------------
// 128 threads, 64 m-rows per CTA, x split to bf16 hi/lo on the fly.
#define XPAD 40   // smem row stride (u16) for 32-wide k chunks

__global__ __launch_bounds__(128) void proj_mma(const float* __restrict__ x) {
    __shared__ u16 xs_hi[64 * XPAD], xs_lo[64 * XPAD];
    __shared__ u16 ws_hi[3 * 64 * XPAD], ws_lo[3 * 64 * XPAD];

    const int tid  = threadIdx.x;
    const int lane = tid & 31;
    const int wp   = tid >> 5;
    const int l16  = lane & 15;
    const int m0   = blockIdx.x * 64;
    const int b    = blockIdx.y;

    const u32 xhb = smem_u32(xs_hi), xlb = smem_u32(xs_lo);
    const u32 whb = smem_u32(ws_hi), wlb = smem_u32(ws_lo);

    float acc[3][8][4];
    #pragma unroll
    for (int w = 0; w < 3; w++)
        #pragma unroll
        for (int n = 0; n < 8; n++)
            #pragma unroll
            for (int j = 0; j < 4; j++) acc[w][n][j] = 0.f;

    const float* xb = x + ((size_t)b * TT + m0) * CCH;

    for (int c0 = 0; c0 < CCH; c0 += 32) {
        __syncthreads();
        // stage x chunk 64 rows x 32 k: load fp32, split inline
        {
            int row = tid >> 1, half = (tid & 1) * 16;
            const float* s = xb + (size_t)row * CCH + c0 + half;
            u16* dh = xs_hi + row * XPAD + half;
            u16* dl = xs_lo + row * XPAD + half;
            #pragma unroll
            for (int i = 0; i < 4; i++) {
                float4 v = *reinterpret_cast<const float4*>(s + i * 4);
                u32 h0, l0, h1, l1;
                split2(v.x, v.y, h0, l0);
                split2(v.z, v.w, h1, l1);
                *reinterpret_cast<uint2*>(dh + i * 4) = make_uint2(h0, h1);
                *reinterpret_cast<uint2*>(dl + i * 4) = make_uint2(l0, l1);
            }
        }
        // stage all 3 W^T chunks: 3 x 64 n x 32 k (two uint4 per thread slot!)
        for (int i = tid; i < 3 * 128; i += 128) {
            int w  = i >> 7;
            int c  = i & 127;
            int rr = c >> 1, ko = (c & 1) * 16;
            size_t g = ((size_t)w * HH + rr) * CCH + c0 + ko;
            u16* dh = ws_hi + (w * 64 + rr) * XPAD + ko;
            u16* dl = ws_lo + (w * 64 + rr) * XPAD + ko;
            #pragma unroll
            for (int u = 0; u < 2; u++) {
                *reinterpret_cast<uint4*>(dh + u * 8) =
                    *reinterpret_cast<const uint4*>(g_wt_hi + g + u * 8);
                *reinterpret_cast<uint4*>(dl + u * 8) =
                    *reinterpret_cast<const uint4*>(g_wt_lo + g + u * 8);
            }
        }
        __syncthreads();

        #pragma unroll
        for (int ks = 0; ks < 2; ks++) {
            u32 ah[4], al[4];
            int arow = wp * 16 + (lane & 7) + ((lane >> 3) & 1) * 8;
            u32 aoff = arow * (XPAD * 2) + ks * 32 + (lane >> 4) * 16;
            ldsm_x4(ah, xhb + aoff);
            ldsm_x4(al, xlb + aoff);
            #pragma unroll
            for (int w = 0; w < 3; w++) {
                #pragma unroll
                for (int n = 0; n < 8; n++) {
                    u32 boff = (u32)(w * 64 + n * 8 + (l16 & 7)) * (XPAD * 2) + ks * 32 + (l16 >> 3) * 16;
                    u32 bh[2], bl[2];
                    ldsm_x2(bh, whb + boff);
                    ldsm_x2(bl, wlb + boff);
                    mma_bf16(acc[w][n], ah, bh);
                    mma_bf16(acc[w][n], ah, bl);
                    mma_bf16(acc[w][n], al, bh);
                }
            }
        }
    }

    // epilogue: split accum to bf16 hi/lo, write to k/q/v buffers
    #pragma unroll
    for (int w = 0; w < 3; w++) {
        u16 *dh, *dl;
        float scale = 1.f;
        if (w == 0)      { dh = g_k_hi; dl = g_k_lo; }
        else if (w == 1) { dh = g_q_hi; dl = g_q_lo; scale = 0.125f; }
        else             { dh = g_v_hi; dl = g_v_lo; }
        #pragma unroll
        for (int n = 0; n < 8; n++) {
            int col = n * 8 + (lane & 3) * 2;
            #pragma unroll
            for (int half = 0; half < 2; half++) {
                int row = m0 + wp * 16 + (lane >> 2) + half * 8;
                u32 hi, lo;
                split2(acc[w][n][half * 2] * scale, acc[w][n][half * 2 + 1] * scale, hi, lo);
                size_t o = ((size_t)b * TT + row) * HH + col;
                *reinterpret_cast<u32*>(dh + o) = hi;
                *reinterpret_cast<u32*>(dl + o) = lo;
            }
        }
    }
}

// ---------------- attention: FA2 HMMA + cp.async double buffering -----------
#define APAD 72                 // smem row stride (u16) for 64-col tiles
#define ARR  (64 * APAD)        // u16 per tile array (4608)
#define STG  (4 * ARR)          // u16 per stage (Kh,Kl,Vh,Vl)
#define ATTN_SMEM (2 * STG * 2) // bytes = 73728

__global__ __launch_bounds__(128) void attn_mma(float* __restrict__ out) {
    extern __shared__ u16 dynsm[];

    const int tid  = threadIdx.x;
    const int lane = tid & 31;
    const int wp   = tid >> 5;
    const int l16  = lane & 15;
    const int b    = blockIdx.y;
    const int qt   = gridDim.x - 1 - blockIdx.x;   // longest rows first
    const int q0   = qt * 64;

    u16* buf0 = dynsm;
    const u32 sb0 = smem_u32(dynsm);
    const u32 stg_b[2] = { sb0, sb0 + STG * 2 };   // byte addr of stage base

    // ---- prologue: stage Q into stage-0 K slots, read fragments ----
    {
        const u16* qh = g_q_hi + ((size_t)b * TT + q0) * HH;
        const u16* ql = g_q_lo + ((size_t)b * TT + q0) * HH;
        int row = tid >> 1, half = (tid & 1) * 32;
        #pragma unroll
        for (int i = 0; i < 4; i++) {
            *reinterpret_cast<uint4*>(buf0 + row * APAD + half + i * 8) =
                *reinterpret_cast<const uint4*>(qh + (size_t)row * HH + half + i * 8);
            *reinterpret_cast<uint4*>(buf0 + ARR + row * APAD + half + i * 8) =
                *reinterpret_cast<const uint4*>(ql + (size_t)row * HH + half + i * 8);
        }
    }
    __syncthreads();

    u32 qa_h[4][4], qa_l[4][4];
    {
        int arow = wp * 16 + (lane & 7) + ((lane >> 3) & 1) * 8;
        #pragma unroll
        for (int ks = 0; ks < 4; ks++) {
            u32 off = arow * (APAD * 2) + ks * 32 + (lane >> 4) * 16;
            ldsm_x4(qa_h[ks], stg_b[0] + off);
            ldsm_x4(qa_l[ks], stg_b[0] + ARR * 2 + off);
        }
    }
    __syncthreads();   // Q fragment reads done before cp.async overwrites stage 0

    const int n_kt = qt + 1;

    // issue prefetch of tile 0 into stage 0
    {
        const size_t base = ((size_t)b * TT + 0) * HH;
        const u16* srcs[4] = { g_k_hi + base, g_k_lo + base, g_v_hi + base, g_v_lo + base };
        #pragma unroll
        for (int a = 0; a < 4; a++) {
            u32 dstb = stg_b[0] + a * ARR * 2;
            #pragma unroll
            for (int i = 0; i < 4; i++) {
                int c = tid + i * 128;
                int row = c >> 3, col = c & 7;
                cpa16(dstb + row * (APAD * 2) + col * 16, srcs[a] + (size_t)row * HH + col * 8);
            }
        }
        CP_COMMIT();
    }

    float Oacc[8][4];
    #pragma unroll
    for (int n = 0; n < 8; n++)
        #pragma unroll
        for (int j = 0; j < 4; j++) Oacc[n][j] = 0.f;

    float mrow[2] = { -1e30f, -1e30f };
    float lrow[2] = { 0.f, 0.f };
    const int qrow0 = q0 + wp * 16 + (lane >> 2);

    for (int kt = 0; kt < n_kt; kt++) {
        // prefetch kt+1
        if (kt + 1 < n_kt) {
            const size_t base = ((size_t)b * TT + (kt + 1) * 64) * HH;
            const u16* srcs[4] = { g_k_hi + base, g_k_lo + base, g_v_hi + base, g_v_lo + base };
            u32 sbase = stg_b[(kt + 1) & 1];
            #pragma unroll
            for (int a = 0; a < 4; a++) {
                u32 dstb = sbase + a * ARR * 2;
                #pragma unroll
                for (int i = 0; i < 4; i++) {
                    int c = tid + i * 128;
                    int row = c >> 3, col = c & 7;
                    cpa16(dstb + row * (APAD * 2) + col * 16, srcs[a] + (size_t)row * HH + col * 8);
                }
            }
            CP_COMMIT();
            CP_WAIT1();
        } else {
            CP_WAIT0();
        }
        __syncthreads();

        const u32 khb = stg_b[kt & 1];
        const u32 klb = khb + ARR * 2;
        const u32 vhb = khb + ARR * 4;
        const u32 vlb = khb + ARR * 6;

        // ---- S = Q K^T (3-term split) ----
        float S[8][4];
        #pragma unroll
        for (int n = 0; n < 8; n++)
            #pragma unroll
            for (int j = 0; j < 4; j++) S[n][j] = 0.f;

        #pragma unroll
        for (int n = 0; n < 8; n++) {
            #pragma unroll
            for (int ks = 0; ks < 4; ks++) {
                u32 boff = (u32)(n * 8 + (l16 & 7)) * (APAD * 2) + ks * 32 + (l16 >> 3) * 16;
                u32 bh[2], bl[2];
                ldsm_x2(bh, khb + boff);
                ldsm_x2(bl, klb + boff);
                mma_bf16(S[n], qa_h[ks], bh);
                mma_bf16(S[n], qa_h[ks], bl);
                mma_bf16(S[n], qa_l[ks], bh);
            }
        }

        // ---- causal mask (diagonal tile only) ----
        if (kt == qt) {
            const int k0 = kt * 64;
            #pragma unroll
            for (int n = 0; n < 8; n++) {
                int colb = k0 + n * 8 + (lane & 3) * 2;
                #pragma unroll
                for (int j = 0; j < 4; j++) {
                    int col = colb + (j & 1);
                    int row = qrow0 + (j >> 1) * 8;
                    if (col > row) S[n][j] = -1e30f;
                }
            }
        }

        // ---- online softmax ----
        float fac[2];
        #pragma unroll
        for (int h = 0; h < 2; h++) {
            float mx = -1e30f;
            #pragma unroll
            for (int n = 0; n < 8; n++)
                mx = fmaxf(mx, fmaxf(S[n][h * 2], S[n][h * 2 + 1]));
            mx = fmaxf(mx, __shfl_xor_sync(0xffffffffu, mx, 1));
            mx = fmaxf(mx, __shfl_xor_sync(0xffffffffu, mx, 2));
            float mnew = fmaxf(mrow[h], mx);
            fac[h] = __expf(mrow[h] - mnew);
            mrow[h] = mnew;
            float sum = 0.f;
            #pragma unroll
            for (int n = 0; n < 8; n++) {
                float p0 = __expf(S[n][h * 2]     - mnew);
                float p1 = __expf(S[n][h * 2 + 1] - mnew);
                S[n][h * 2] = p0;
                S[n][h * 2 + 1] = p1;
                sum += p0 + p1;
            }
            sum += __shfl_xor_sync(0xffffffffu, sum, 1);
            sum += __shfl_xor_sync(0xffffffffu, sum, 2);
            lrow[h] = lrow[h] * fac[h] + sum;
            #pragma unroll
            for (int n = 0; n < 8; n++) {
                Oacc[n][h * 2]     *= fac[h];
                Oacc[n][h * 2 + 1] *= fac[h];
            }
        }

        // ---- O += P V (reg->reg pack of P; 3-term split) ----
        #pragma unroll
        for (int ks = 0; ks < 4; ks++) {
            u32 pa_h[4], pa_l[4];
            #pragma unroll
            for (int j = 0; j < 4; j++) {
                int n = 2 * ks + (j >> 1);
                int base = (j & 1) * 2;
                split2(S[n][base], S[n][base + 1], pa_h[j], pa_l[j]);
            }
            #pragma unroll
            for (int n = 0; n < 8; n++) {
                u32 voff = (u32)(ks * 16 + l16) * (APAD * 2) + n * 16;
                u32 bh[2], bl[2];
                ldsm_x2t(bh, vhb + voff);
                ldsm_x2t(bl, vlb + voff);
                mma_bf16(Oacc[n], pa_h, bh);
                mma_bf16(Oacc[n], pa_h, bl);
                mma_bf16(Oacc[n], pa_l, bh);
            }
        }
        __syncthreads();   // all reads of this stage done before it is re-filled
    }

    // ---- finalize ----
    float inv0 = 1.f / lrow[0];
    float inv1 = 1.f / lrow[1];
    #pragma unroll
    for (int n = 0; n < 8; n++) {
        int col = n * 8 + (lane & 3) * 2;
        int row0 = q0 + wp * 16 + (lane >> 2);
        float2 v0 = make_float2(Oacc[n][0] * inv0, Oacc[n][1] * inv0);
        float2 v1 = make_float2(Oacc[n][2] * inv1, Oacc[n][3] * inv1);
        *reinterpret_cast<float2*>(out + ((size_t)b * TT + row0) * HH + col) = v0;
        *reinterpret_cast<float2*>(out + ((size_t)b * TT + row0 + 8) * HH + col) = v1;
    }
}

// ---------------------------------------------------------------------------
extern "C" void kernel_launch(void* const* d_in, const int* in_sizes, int n_in,
                              void* d_out, int out_size)
{
    const float* x  = (const float*)d_in[0];
    const float* Wk = (const float*)d_in[1];
    const float* Wq = (const float*)d_in[2];
    const float* Wv = (const float*)d_in[3];
    float* out = (float*)d_out;
    (void)in_sizes; (void)n_in; (void)out_size;

    split_w<<<(3 * HH * CCH) / 256, 256>>>(Wk, Wq, Wv);

    dim3 gridP(TT / 64, BB);
    proj_mma<<<gridP, 128>>>(x);

    static int attr_set = 0;
    if (!attr_set) {
        cudaFuncSetAttribute(attn_mma, cudaFuncAttributeMaxDynamicSharedMemorySize, ATTN_SMEM);
        attr_set = 1;
    }
    dim3 gridA(TT / 64, BB);
    attn_mma<<<gridA, 128, ATTN_SMEM>>>(out);
}

// round 10
// speedup vs baseline: 4.7027x; 1.0697x over previous
#include <cuda_runtime.h>
#include <cuda_bf16.h>
#include <cstdint>

#define BB 32
#define TT 2048
#define CCH 384
#define HH 64

typedef unsigned int u32;
typedef unsigned short u16;

// ---------------- global split-bf16 buffers (static: no allocs) -------------
__device__ __align__(16) u16 g_wt_hi[3 * HH * CCH];   // [w][n][k] transposed
__device__ __align__(16) u16 g_wt_lo[3 * HH * CCH];
__device__ __align__(16) u16 g_q_hi[BB * TT * HH];    // q pre-scaled by 1/8
__device__ __align__(16) u16 g_q_lo[BB * TT * HH];
__device__ __align__(16) u16 g_k_hi[BB * TT * HH];
__device__ __align__(16) u16 g_k_lo[BB * TT * HH];
__device__ __align__(16) u16 g_v_hi[BB * TT * HH];
__device__ __align__(16) u16 g_v_lo[BB * TT * HH];

// ---------------- helpers ---------------------------------------------------
static __device__ __forceinline__ u32 smem_u32(const void* p) {
    u32 a;
    asm("{ .reg .u64 t; cvta.to.shared.u64 t, %1; cvt.u32.u64 %0, t; }" : "=r"(a) : "l"(p));
    return a;
}
static __device__ __forceinline__ void ldsm_x4(u32 r[4], u32 a) {
    asm volatile("ldmatrix.sync.aligned.m8n8.x4.shared.b16 {%0,%1,%2,%3}, [%4];"
                 : "=r"(r[0]), "=r"(r[1]), "=r"(r[2]), "=r"(r[3]) : "r"(a));
}
static __device__ __forceinline__ void ldsm_x2(u32 r[2], u32 a) {
    asm volatile("ldmatrix.sync.aligned.m8n8.x2.shared.b16 {%0,%1}, [%2];"
                 : "=r"(r[0]), "=r"(r[1]) : "r"(a));
}
static __device__ __forceinline__ void ldsm_x2t(u32 r[2], u32 a) {
    asm volatile("ldmatrix.sync.aligned.m8n8.x2.trans.shared.b16 {%0,%1}, [%2];"
                 : "=r"(r[0]), "=r"(r[1]) : "r"(a));
}
static __device__ __forceinline__ void mma_bf16(float d[4], const u32 a[4], const u32 b[2]) {
    asm volatile("mma.sync.aligned.m16n8k16.row.col.f32.bf16.bf16.f32 "
                 "{%0,%1,%2,%3}, {%4,%5,%6,%7}, {%8,%9}, {%0,%1,%2,%3};"
                 : "+f"(d[0]), "+f"(d[1]), "+f"(d[2]), "+f"(d[3])
                 : "r"(a[0]), "r"(a[1]), "r"(a[2]), "r"(a[3]), "r"(b[0]), "r"(b[1]));
}
static __device__ __forceinline__ u32 packbf2(float a, float b) {
    __nv_bfloat162 v;
    v.x = __float2bfloat16(a);
    v.y = __float2bfloat16(b);
    return *reinterpret_cast<u32*>(&v);
}
static __device__ __forceinline__ void split2(float a, float b, u32& hi, u32& lo) {
    float ha = __bfloat162float(__float2bfloat16(a));
    float hb = __bfloat162float(__float2bfloat16(b));
    hi = packbf2(ha, hb);
    lo = packbf2(a - ha, b - hb);
}
static __device__ __forceinline__ void cpa16(u32 dst, const void* src) {
    asm volatile("cp.async.cg.shared.global [%0], [%1], 16;" :: "r"(dst), "l"(src));
}
#define CP_COMMIT() asm volatile("cp.async.commit_group;" ::: "memory")
#define CP_WAIT1()  asm volatile("cp.async.wait_group 1;" ::: "memory")
#define CP_WAIT0()  asm volatile("cp.async.wait_group 0;" ::: "memory")

// ---------------- prepass: split + transpose weights ------------------------
__global__ __launch_bounds__(256) void split_w(const float* __restrict__ Wk,
                                               const float* __restrict__ Wq,
                                               const float* __restrict__ Wv) {
    int id = blockIdx.x * blockDim.x + threadIdx.x;   // < 3*64*384
    int w = id / (HH * CCH);
    int r = id % (HH * CCH);
    int n = r / CCH;
    int k = r % CCH;
    const float* W = (w == 0) ? Wk : (w == 1) ? Wq : Wv;
    float v = W[k * HH + n];
    float h = __bfloat162float(__float2bfloat16(v));
    __nv_bfloat16 bh = __float2bfloat16(h);
    __nv_bfloat16 bl = __float2bfloat16(v - h);
    g_wt_hi[id] = *reinterpret_cast<u16*>(&bh);
    g_wt_lo[id] = *reinterpret_cast<u16*>(&bl);
}

// ---------------- projection: q/k/v = x @ W, fused 3 weights ----------------
// 128 threads, 64 m-rows per CTA, x split to bf16 hi/lo on the fly.
#define XPAD 40   // smem row stride (u16) for 32-wide k chunks

__global__ __launch_bounds__(128) void proj_mma(const float* __restrict__ x) {
    __shared__ u16 xs_hi[64 * XPAD], xs_lo[64 * XPAD];
    __shared__ u16 ws_hi[3 * 64 * XPAD], ws_lo[3 * 64 * XPAD];

    const int tid  = threadIdx.x;
    const int lane = tid & 31;
    const int wp   = tid >> 5;
    const int l16  = lane & 15;
    const int m0   = blockIdx.x * 64;
    const int b    = blockIdx.y;

    const u32 xhb = smem_u32(xs_hi), xlb = smem_u32(xs_lo);
    const u32 whb = smem_u32(ws_hi), wlb = smem_u32(ws_lo);

    float acc[3][8][4];
    #pragma unroll
    for (int w = 0; w < 3; w++)
        #pragma unroll
        for (int n = 0; n < 8; n++)
            #pragma unroll
            for (int j = 0; j < 4; j++) acc[w][n][j] = 0.f;

    const float* xb = x + ((size_t)b * TT + m0) * CCH;

    for (int c0 = 0; c0 < CCH; c0 += 32) {
        __syncthreads();
        // stage x chunk 64 rows x 32 k: load fp32, split inline
        {
            int row = tid >> 1, half = (tid & 1) * 16;
            const float* s = xb + (size_t)row * CCH + c0 + half;
            u16* dh = xs_hi + row * XPAD + half;
            u16* dl = xs_lo + row * XPAD + half;
            #pragma unroll
            for (int i = 0; i < 4; i++) {
                float4 v = *reinterpret_cast<const float4*>(s + i * 4);
                u32 h0, l0, h1, l1;
                split2(v.x, v.y, h0, l0);
                split2(v.z, v.w, h1, l1);
                *reinterpret_cast<uint2*>(dh + i * 4) = make_uint2(h0, h1);
                *reinterpret_cast<uint2*>(dl + i * 4) = make_uint2(l0, l1);
            }
        }
        // stage all 3 W^T chunks: 3 x 64 n x 32 k (two uint4 per thread slot)
        for (int i = tid; i < 3 * 128; i += 128) {
            int w  = i >> 7;
            int c  = i & 127;
            int rr = c >> 1, ko = (c & 1) * 16;
            size_t g = ((size_t)w * HH + rr) * CCH + c0 + ko;
            u16* dh = ws_hi + (w * 64 + rr) * XPAD + ko;
            u16* dl = ws_lo + (w * 64 + rr) * XPAD + ko;
            #pragma unroll
            for (int u = 0; u < 2; u++) {
                *reinterpret_cast<uint4*>(dh + u * 8) =
                    *reinterpret_cast<const uint4*>(g_wt_hi + g + u * 8);
                *reinterpret_cast<uint4*>(dl + u * 8) =
                    *reinterpret_cast<const uint4*>(g_wt_lo + g + u * 8);
            }
        }
        __syncthreads();

        #pragma unroll
        for (int ks = 0; ks < 2; ks++) {
            u32 ah[4], al[4];
            int arow = wp * 16 + (lane & 7) + ((lane >> 3) & 1) * 8;
            u32 aoff = arow * (XPAD * 2) + ks * 32 + (lane >> 4) * 16;
            ldsm_x4(ah, xhb + aoff);
            ldsm_x4(al, xlb + aoff);
            #pragma unroll
            for (int w = 0; w < 3; w++) {
                #pragma unroll
                for (int n = 0; n < 8; n++) {
                    u32 boff = (u32)(w * 64 + n * 8 + (l16 & 7)) * (XPAD * 2) + ks * 32 + (l16 >> 3) * 16;
                    u32 bh[2], bl[2];
                    ldsm_x2(bh, whb + boff);
                    ldsm_x2(bl, wlb + boff);
                    mma_bf16(acc[w][n], ah, bh);
                    mma_bf16(acc[w][n], ah, bl);
                    mma_bf16(acc[w][n], al, bh);
                }
            }
        }
    }

    // epilogue: split accum to bf16 hi/lo, write to k/q/v buffers
    #pragma unroll
    for (int w = 0; w < 3; w++) {
        u16 *dh, *dl;
        float scale = 1.f;
        if (w == 0)      { dh = g_k_hi; dl = g_k_lo; }
        else if (w == 1) { dh = g_q_hi; dl = g_q_lo; scale = 0.125f; }
        else             { dh = g_v_hi; dl = g_v_lo; }
        #pragma unroll
        for (int n = 0; n < 8; n++) {
            int col = n * 8 + (lane & 3) * 2;
            #pragma unroll
            for (int half = 0; half < 2; half++) {
                int row = m0 + wp * 16 + (lane >> 2) + half * 8;
                u32 hi, lo;
                split2(acc[w][n][half * 2] * scale, acc[w][n][half * 2 + 1] * scale, hi, lo);
                size_t o = ((size_t)b * TT + row) * HH + col;
                *reinterpret_cast<u32*>(dh + o) = hi;
                *reinterpret_cast<u32*>(dl + o) = lo;
            }
        }
    }
}

// ---------------- attention: FA2 HMMA + cp.async, XOR-swizzled smem ---------
// Tile row layout: 64 rows x 64 u16 = 128B/row; 16B chunk c at (row, c) lives
// at byte row*128 + ((c ^ (row & 7)) * 16). Conflict-free for all ldsm phases
// and cp.async fills used below.
#define ARRB 8192               // bytes per 64x64 u16 tile
#define STGB (4 * ARRB)         // bytes per stage (Kh,Kl,Vh,Vl) = 32768
#define ATTN_SMEM (2 * STGB)    // 65536

#define SWX(row, c) ((u32)(row) * 128u + (u32)(((c) ^ ((row) & 7)) * 16))

__global__ __launch_bounds__(128, 3) void attn_mma(float* __restrict__ out) {
    extern __shared__ u16 dynsm[];

    const int tid  = threadIdx.x;
    const int lane = tid & 31;
    const int wp   = tid >> 5;
    const int l16  = lane & 15;
    const int b    = blockIdx.y;
    const int qt   = gridDim.x - 1 - blockIdx.x;   // longest rows first
    const int q0   = qt * 64;

    const u32 sb0 = smem_u32(dynsm);
    const u32 stg_b[2] = { sb0, sb0 + STGB };
    const int n_kt = qt + 1;

    // ---- front-load prefetch of tile 0 into stage 1 (overlaps Q prologue) --
    {
        const size_t base = ((size_t)b * TT + 0) * HH;
        const u16* srcs[4] = { g_k_hi + base, g_k_lo + base, g_v_hi + base, g_v_lo + base };
        #pragma unroll
        for (int a = 0; a < 4; a++) {
            u32 dstb = stg_b[1] + a * ARRB;
            #pragma unroll
            for (int i = 0; i < 4; i++) {
                int c = tid + i * 128;
                int row = c >> 3, col = c & 7;
                cpa16(dstb + SWX(row, col), srcs[a] + (size_t)row * HH + col * 8);
            }
        }
        CP_COMMIT();
    }

    // ---- prologue: stage Q into stage-0 first two slots, read fragments ----
    {
        const u16* qh = g_q_hi + ((size_t)b * TT + q0) * HH;
        const u16* ql = g_q_lo + ((size_t)b * TT + q0) * HH;
        int row = tid >> 1, cbase = (tid & 1) * 4;
        #pragma unroll
        for (int i = 0; i < 4; i++) {
            int c = cbase + i;
            *reinterpret_cast<uint4*>((char*)dynsm + SWX(row, c)) =
                *reinterpret_cast<const uint4*>(qh + (size_t)row * HH + c * 8);
            *reinterpret_cast<uint4*>((char*)dynsm + ARRB + SWX(row, c)) =
                *reinterpret_cast<const uint4*>(ql + (size_t)row * HH + c * 8);
        }
    }
    __syncthreads();

    u32 qa_h[4][4], qa_l[4][4];
    {
        int arow = wp * 16 + (lane & 7) + ((lane >> 3) & 1) * 8;
        #pragma unroll
        for (int ks = 0; ks < 4; ks++) {
            int c = ks * 2 + (lane >> 4);
            ldsm_x4(qa_h[ks], stg_b[0] + SWX(arow, c));
            ldsm_x4(qa_l[ks], stg_b[0] + ARRB + SWX(arow, c));
        }
    }
    __syncthreads();   // Q reads done before stage 0 is reused by prefetch

    float Oacc[8][4];
    #pragma unroll
    for (int n = 0; n < 8; n++)
        #pragma unroll
        for (int j = 0; j < 4; j++) Oacc[n][j] = 0.f;

    float mrow[2] = { -1e30f, -1e30f };
    float lrow[2] = { 0.f, 0.f };
    const int qrow0 = q0 + wp * 16 + (lane >> 2);

    for (int kt = 0; kt < n_kt; kt++) {
        // tile kt lives in stage (kt+1)&1; prefetch kt+1 into stage kt&1
        if (kt + 1 < n_kt) {
            const size_t base = ((size_t)b * TT + (kt + 1) * 64) * HH;
            const u16* srcs[4] = { g_k_hi + base, g_k_lo + base, g_v_hi + base, g_v_lo + base };
            u32 sbase = stg_b[kt & 1];
            #pragma unroll
            for (int a = 0; a < 4; a++) {
                u32 dstb = sbase + a * ARRB;
                #pragma unroll
                for (int i = 0; i < 4; i++) {
                    int c = tid + i * 128;
                    int row = c >> 3, col = c & 7;
                    cpa16(dstb + SWX(row, col), srcs[a] + (size_t)row * HH + col * 8);
                }
            }
            CP_COMMIT();
            CP_WAIT1();
        } else {
            CP_WAIT0();
        }
        __syncthreads();

        const u32 khb = stg_b[(kt + 1) & 1];
        const u32 klb = khb + ARRB;
        const u32 vhb = khb + 2 * ARRB;
        const u32 vlb = khb + 3 * ARRB;

        // ---- S = Q K^T (3-term split) ----
        float S[8][4];
        #pragma unroll
        for (int n = 0; n < 8; n++)
            #pragma unroll
            for (int j = 0; j < 4; j++) S[n][j] = 0.f;

        #pragma unroll
        for (int n = 0; n < 8; n++) {
            int brow = n * 8 + (l16 & 7);
            #pragma unroll
            for (int ks = 0; ks < 4; ks++) {
                int c = ks * 2 + (l16 >> 3);
                u32 boff = SWX(brow, c);
                u32 bh[2], bl[2];
                ldsm_x2(bh, khb + boff);
                ldsm_x2(bl, klb + boff);
                mma_bf16(S[n], qa_h[ks], bh);
                mma_bf16(S[n], qa_h[ks], bl);
                mma_bf16(S[n], qa_l[ks], bh);
            }
        }

        // ---- causal mask (diagonal tile only) ----
        if (kt == qt) {
            const int k0 = kt * 64;
            #pragma unroll
            for (int n = 0; n < 8; n++) {
                int colb = k0 + n * 8 + (lane & 3) * 2;
                #pragma unroll
                for (int j = 0; j < 4; j++) {
                    int col = colb + (j & 1);
                    int row = qrow0 + (j >> 1) * 8;
                    if (col > row) S[n][j] = -1e30f;
                }
            }
        }

        // ---- online softmax ----
        float fac[2];
        #pragma unroll
        for (int h = 0; h < 2; h++) {
            float mx = -1e30f;
            #pragma unroll
            for (int n = 0; n < 8; n++)
                mx = fmaxf(mx, fmaxf(S[n][h * 2], S[n][h * 2 + 1]));
            mx = fmaxf(mx, __shfl_xor_sync(0xffffffffu, mx, 1));
            mx = fmaxf(mx, __shfl_xor_sync(0xffffffffu, mx, 2));
            float mnew = fmaxf(mrow[h], mx);
            fac[h] = __expf(mrow[h] - mnew);
            mrow[h] = mnew;
            float sum = 0.f;
            #pragma unroll
            for (int n = 0; n < 8; n++) {
                float p0 = __expf(S[n][h * 2]     - mnew);
                float p1 = __expf(S[n][h * 2 + 1] - mnew);
                S[n][h * 2] = p0;
                S[n][h * 2 + 1] = p1;
                sum += p0 + p1;
            }
            sum += __shfl_xor_sync(0xffffffffu, sum, 1);
            sum += __shfl_xor_sync(0xffffffffu, sum, 2);
            lrow[h] = lrow[h] * fac[h] + sum;
            #pragma unroll
            for (int n = 0; n < 8; n++) {
                Oacc[n][h * 2]     *= fac[h];
                Oacc[n][h * 2 + 1] *= fac[h];
            }
        }

        // ---- O += P V (reg->reg pack of P; 3-term split) ----
        #pragma unroll
        for (int ks = 0; ks < 4; ks++) {
            u32 pa_h[4], pa_l[4];
            #pragma unroll
            for (int j = 0; j < 4; j++) {
                int n = 2 * ks + (j >> 1);
                int base = (j & 1) * 2;
                split2(S[n][base], S[n][base + 1], pa_h[j], pa_l[j]);
            }
            int vrow = ks * 16 + l16;
            #pragma unroll
            for (int n = 0; n < 8; n++) {
                u32 voff = SWX(vrow, n);
                u32 bh[2], bl[2];
                ldsm_x2t(bh, vhb + voff);
                ldsm_x2t(bl, vlb + voff);
                mma_bf16(Oacc[n], pa_h, bh);
                mma_bf16(Oacc[n], pa_h, bl);
                mma_bf16(Oacc[n], pa_l, bh);
            }
        }
        __syncthreads();   // all reads of this stage done before it is re-filled
    }

    // ---- finalize ----
    float inv0 = 1.f / lrow[0];
    float inv1 = 1.f / lrow[1];
    #pragma unroll
    for (int n = 0; n < 8; n++) {
        int col = n * 8 + (lane & 3) * 2;
        int row0 = q0 + wp * 16 + (lane >> 2);
        float2 v0 = make_float2(Oacc[n][0] * inv0, Oacc[n][1] * inv0);
        float2 v1 = make_float2(Oacc[n][2] * inv1, Oacc[n][3] * inv1);
        *reinterpret_cast<float2*>(out + ((size_t)b * TT + row0) * HH + col) = v0;
        *reinterpret_cast<float2*>(out + ((size_t)b * TT + row0 + 8) * HH + col) = v1;
    }
}

// ---------------------------------------------------------------------------
extern "C" void kernel_launch(void* const* d_in, const int* in_sizes, int n_in,
                              void* d_out, int out_size)
{
    const float* x  = (const float*)d_in[0];
    const float* Wk = (const float*)d_in[1];
    const float* Wq = (const float*)d_in[2];
    const float* Wv = (const float*)d_in[3];
    float* out = (float*)d_out;
    (void)in_sizes; (void)n_in; (void)out_size;

    split_w<<<(3 * HH * CCH) / 256, 256>>>(Wk, Wq, Wv);

    dim3 gridP(TT / 64, BB);
    proj_mma<<<gridP, 128>>>(x);

    static int attr_set = 0;
    if (!attr_set) {
        cudaFuncSetAttribute(attn_mma, cudaFuncAttributeMaxDynamicSharedMemorySize, ATTN_SMEM);
        attr_set = 1;
    }
    dim3 gridA(TT / 64, BB);
    attn_mma<<<gridA, 128, ATTN_SMEM>>>(out);
}

// round 11
// speedup vs baseline: 4.9266x; 1.0476x over previous
#include <cuda_runtime.h>
#include <cuda_bf16.h>
#include <cstdint>

#define BB 32
#define TT 2048
#define CCH 384
#define HH 64

typedef unsigned int u32;
typedef unsigned short u16;

// ---------------- global split-bf16 buffers (static: no allocs) -------------
__device__ __align__(16) u16 g_wt_hi[3 * HH * CCH];   // [w][n][k] transposed
__device__ __align__(16) u16 g_wt_lo[3 * HH * CCH];
__device__ __align__(16) u16 g_q_hi[BB * TT * HH];    // q pre-scaled by log2e/8
__device__ __align__(16) u16 g_q_lo[BB * TT * HH];
__device__ __align__(16) u16 g_k_hi[BB * TT * HH];
__device__ __align__(16) u16 g_k_lo[BB * TT * HH];
__device__ __align__(16) u16 g_v_hi[BB * TT * HH];
__device__ __align__(16) u16 g_v_lo[BB * TT * HH];

// ---------------- helpers ---------------------------------------------------
static __device__ __forceinline__ u32 smem_u32(const void* p) {
    u32 a;
    asm("{ .reg .u64 t; cvta.to.shared.u64 t, %1; cvt.u32.u64 %0, t; }" : "=r"(a) : "l"(p));
    return a;
}
static __device__ __forceinline__ void ldsm_x4(u32 r[4], u32 a) {
    asm volatile("ldmatrix.sync.aligned.m8n8.x4.shared.b16 {%0,%1,%2,%3}, [%4];"
                 : "=r"(r[0]), "=r"(r[1]), "=r"(r[2]), "=r"(r[3]) : "r"(a));
}
static __device__ __forceinline__ void ldsm_x2(u32 r[2], u32 a) {
    asm volatile("ldmatrix.sync.aligned.m8n8.x2.shared.b16 {%0,%1}, [%2];"
                 : "=r"(r[0]), "=r"(r[1]) : "r"(a));
}
static __device__ __forceinline__ void ldsm_x2t(u32 r[2], u32 a) {
    asm volatile("ldmatrix.sync.aligned.m8n8.x2.trans.shared.b16 {%0,%1}, [%2];"
                 : "=r"(r[0]), "=r"(r[1]) : "r"(a));
}
static __device__ __forceinline__ void mma_bf16(float d[4], const u32 a[4], const u32 b[2]) {
    asm volatile("mma.sync.aligned.m16n8k16.row.col.f32.bf16.bf16.f32 "
                 "{%0,%1,%2,%3}, {%4,%5,%6,%7}, {%8,%9}, {%0,%1,%2,%3};"
                 : "+f"(d[0]), "+f"(d[1]), "+f"(d[2]), "+f"(d[3])
                 : "r"(a[0]), "r"(a[1]), "r"(a[2]), "r"(a[3]), "r"(b[0]), "r"(b[1]));
}
// split a,b into bf16 hi pair + bf16 lo pair (rn rounding, matches __float2bfloat16)
static __device__ __forceinline__ void split2(float a, float b, u32& hi, u32& lo) {
    u32 h;
    asm("cvt.rn.bf16x2.f32 %0, %1, %2;" : "=r"(h) : "f"(b), "f"(a)); // upper=b, lower=a
    float ha = __uint_as_float(h << 16);
    float hb = __uint_as_float(h & 0xffff0000u);
    float la = a - ha;
    float lb = b - hb;
    asm("cvt.rn.bf16x2.f32 %0, %1, %2;" : "=r"(lo) : "f"(lb), "f"(la));
    hi = h;
}
static __device__ __forceinline__ float ex2(float x) {
    float y;
    asm("ex2.approx.ftz.f32 %0, %1;" : "=f"(y) : "f"(x));
    return y;
}
static __device__ __forceinline__ void cpa16(u32 dst, const void* src) {
    asm volatile("cp.async.cg.shared.global [%0], [%1], 16;" :: "r"(dst), "l"(src));
}
#define CP_COMMIT() asm volatile("cp.async.commit_group;" ::: "memory")
#define CP_WAIT1()  asm volatile("cp.async.wait_group 1;" ::: "memory")
#define CP_WAIT0()  asm volatile("cp.async.wait_group 0;" ::: "memory")

#define QSCALE 0.18033688011112042f   // (1/8) * log2(e)

// ---------------- prepass: split + transpose weights ------------------------
__global__ __launch_bounds__(256) void split_w(const float* __restrict__ Wk,
                                               const float* __restrict__ Wq,
                                               const float* __restrict__ Wv) {
    int id = blockIdx.x * blockDim.x + threadIdx.x;   // < 3*64*384
    int w = id / (HH * CCH);
    int r = id % (HH * CCH);
    int n = r / CCH;
    int k = r % CCH;
    const float* W = (w == 0) ? Wk : (w == 1) ? Wq : Wv;
    float v = W[k * HH + n];
    float h = __bfloat162float(__float2bfloat16(v));
    __nv_bfloat16 bh = __float2bfloat16(h);
    __nv_bfloat16 bl = __float2bfloat16(v - h);
    g_wt_hi[id] = *reinterpret_cast<u16*>(&bh);
    g_wt_lo[id] = *reinterpret_cast<u16*>(&bl);
}

// ---------------- projection: q/k/v = x @ W, fused 3 weights ----------------
// 128 threads, 64 m-rows per CTA, x split to bf16 hi/lo on the fly.
#define XPAD 40   // smem row stride (u16) for 32-wide k chunks

__global__ __launch_bounds__(128, 3) void proj_mma(const float* __restrict__ x) {
    __shared__ u16 xs_hi[64 * XPAD], xs_lo[64 * XPAD];
    __shared__ u16 ws_hi[3 * 64 * XPAD], ws_lo[3 * 64 * XPAD];

    const int tid  = threadIdx.x;
    const int lane = tid & 31;
    const int wp   = tid >> 5;
    const int l16  = lane & 15;
    const int m0   = blockIdx.x * 64;
    const int b    = blockIdx.y;

    const u32 xhb = smem_u32(xs_hi), xlb = smem_u32(xs_lo);
    const u32 whb = smem_u32(ws_hi), wlb = smem_u32(ws_lo);

    float acc[3][8][4];
    #pragma unroll
    for (int w = 0; w < 3; w++)
        #pragma unroll
        for (int n = 0; n < 8; n++)
            #pragma unroll
            for (int j = 0; j < 4; j++) acc[w][n][j] = 0.f;

    const float* xb = x + ((size_t)b * TT + m0) * CCH;

    for (int c0 = 0; c0 < CCH; c0 += 32) {
        __syncthreads();
        // stage x chunk 64 rows x 32 k: load fp32, split inline
        {
            int row = tid >> 1, half = (tid & 1) * 16;
            const float* s = xb + (size_t)row * CCH + c0 + half;
            u16* dh = xs_hi + row * XPAD + half;
            u16* dl = xs_lo + row * XPAD + half;
            #pragma unroll
            for (int i = 0; i < 4; i++) {
                float4 v = *reinterpret_cast<const float4*>(s + i * 4);
                u32 h0, l0, h1, l1;
                split2(v.x, v.y, h0, l0);
                split2(v.z, v.w, h1, l1);
                *reinterpret_cast<uint2*>(dh + i * 4) = make_uint2(h0, h1);
                *reinterpret_cast<uint2*>(dl + i * 4) = make_uint2(l0, l1);
            }
        }
        // stage all 3 W^T chunks: 3 x 64 n x 32 k (two uint4 per thread slot)
        for (int i = tid; i < 3 * 128; i += 128) {
            int w  = i >> 7;
            int c  = i & 127;
            int rr = c >> 1, ko = (c & 1) * 16;
            size_t g = ((size_t)w * HH + rr) * CCH + c0 + ko;
            u16* dh = ws_hi + (w * 64 + rr) * XPAD + ko;
            u16* dl = ws_lo + (w * 64 + rr) * XPAD + ko;
            #pragma unroll
            for (int u = 0; u < 2; u++) {
                *reinterpret_cast<uint4*>(dh + u * 8) =
                    *reinterpret_cast<const uint4*>(g_wt_hi + g + u * 8);
                *reinterpret_cast<uint4*>(dl + u * 8) =
                    *reinterpret_cast<const uint4*>(g_wt_lo + g + u * 8);
            }
        }
        __syncthreads();

        #pragma unroll
        for (int ks = 0; ks < 2; ks++) {
            u32 ah[4], al[4];
            int arow = wp * 16 + (lane & 7) + ((lane >> 3) & 1) * 8;
            u32 aoff = arow * (XPAD * 2) + ks * 32 + (lane >> 4) * 16;
            ldsm_x4(ah, xhb + aoff);
            ldsm_x4(al, xlb + aoff);
            #pragma unroll
            for (int w = 0; w < 3; w++) {
                #pragma unroll
                for (int n = 0; n < 8; n++) {
                    u32 boff = (u32)(w * 64 + n * 8 + (l16 & 7)) * (XPAD * 2) + ks * 32 + (l16 >> 3) * 16;
                    u32 bh[2], bl[2];
                    ldsm_x2(bh, whb + boff);
                    ldsm_x2(bl, wlb + boff);
                    mma_bf16(acc[w][n], ah, bh);
                    mma_bf16(acc[w][n], ah, bl);
                    mma_bf16(acc[w][n], al, bh);
                }
            }
        }
    }

    // epilogue: split accum to bf16 hi/lo, write to k/q/v buffers
    #pragma unroll
    for (int w = 0; w < 3; w++) {
        u16 *dh, *dl;
        float scale = 1.f;
        if (w == 0)      { dh = g_k_hi; dl = g_k_lo; }
        else if (w == 1) { dh = g_q_hi; dl = g_q_lo; scale = QSCALE; }
        else             { dh = g_v_hi; dl = g_v_lo; }
        #pragma unroll
        for (int n = 0; n < 8; n++) {
            int col = n * 8 + (lane & 3) * 2;
            #pragma unroll
            for (int half = 0; half < 2; half++) {
                int row = m0 + wp * 16 + (lane >> 2) + half * 8;
                u32 hi, lo;
                split2(acc[w][n][half * 2] * scale, acc[w][n][half * 2 + 1] * scale, hi, lo);
                size_t o = ((size_t)b * TT + row) * HH + col;
                *reinterpret_cast<u32*>(dh + o) = hi;
                *reinterpret_cast<u32*>(dl + o) = lo;
            }
        }
    }
}

// ---------------- attention: FA2 HMMA + cp.async, XOR-swizzled smem ---------
// Tile row layout: 64 rows x 64 u16 = 128B/row; 16B chunk c at (row, c) lives
// at byte row*128 + ((c ^ (row & 7)) * 16).
#define ARRB 8192               // bytes per 64x64 u16 tile
#define STGB (4 * ARRB)         // bytes per stage (Kh,Kl,Vh,Vl) = 32768
#define ATTN_SMEM (2 * STGB)    // 65536

#define SWX(row, c) ((u32)(row) * 128u + (u32)(((c) ^ ((row) & 7)) * 16))

__global__ __launch_bounds__(128, 3) void attn_mma(float* __restrict__ out) {
    extern __shared__ u16 dynsm[];

    const int tid  = threadIdx.x;
    const int lane = tid & 31;
    const int wp   = tid >> 5;
    const int l16  = lane & 15;
    const int b    = blockIdx.y;
    const int qt   = gridDim.x - 1 - blockIdx.x;   // longest rows first
    const int q0   = qt * 64;

    const u32 sb0 = smem_u32(dynsm);
    const u32 stg_b[2] = { sb0, sb0 + STGB };
    const int n_kt = qt + 1;

    // ---- front-load prefetch of tile 0 into stage 1 (overlaps Q prologue) --
    {
        const size_t base = ((size_t)b * TT + 0) * HH;
        const u16* srcs[4] = { g_k_hi + base, g_k_lo + base, g_v_hi + base, g_v_lo + base };
        #pragma unroll
        for (int a = 0; a < 4; a++) {
            u32 dstb = stg_b[1] + a * ARRB;
            #pragma unroll
            for (int i = 0; i < 4; i++) {
                int c = tid + i * 128;
                int row = c >> 3, col = c & 7;
                cpa16(dstb + SWX(row, col), srcs[a] + (size_t)row * HH + col * 8);
            }
        }
        CP_COMMIT();
    }

    // ---- prologue: stage Q into stage-0 first two slots, read fragments ----
    {
        const u16* qh = g_q_hi + ((size_t)b * TT + q0) * HH;
        const u16* ql = g_q_lo + ((size_t)b * TT + q0) * HH;
        int row = tid >> 1, cbase = (tid & 1) * 4;
        #pragma unroll
        for (int i = 0; i < 4; i++) {
            int c = cbase + i;
            *reinterpret_cast<uint4*>((char*)dynsm + SWX(row, c)) =
                *reinterpret_cast<const uint4*>(qh + (size_t)row * HH + c * 8);
            *reinterpret_cast<uint4*>((char*)dynsm + ARRB + SWX(row, c)) =
                *reinterpret_cast<const uint4*>(ql + (size_t)row * HH + c * 8);
        }
    }
    __syncthreads();

    u32 qa_h[4][4], qa_l[4][4];
    {
        int arow = wp * 16 + (lane & 7) + ((lane >> 3) & 1) * 8;
        #pragma unroll
        for (int ks = 0; ks < 4; ks++) {
            int c = ks * 2 + (lane >> 4);
            ldsm_x4(qa_h[ks], stg_b[0] + SWX(arow, c));
            ldsm_x4(qa_l[ks], stg_b[0] + ARRB + SWX(arow, c));
        }
    }
    __syncthreads();   // Q reads done before stage 0 is reused by prefetch

    float Oacc[8][4];
    #pragma unroll
    for (int n = 0; n < 8; n++)
        #pragma unroll
        for (int j = 0; j < 4; j++) Oacc[n][j] = 0.f;

    float mrow[2] = { -1e30f, -1e30f };
    float lrow[2] = { 0.f, 0.f };
    const int qrow0 = q0 + wp * 16 + (lane >> 2);

    for (int kt = 0; kt < n_kt; kt++) {
        // tile kt lives in stage (kt+1)&1; prefetch kt+1 into stage kt&1
        if (kt + 1 < n_kt) {
            const size_t base = ((size_t)b * TT + (kt + 1) * 64) * HH;
            const u16* srcs[4] = { g_k_hi + base, g_k_lo + base, g_v_hi + base, g_v_lo + base };
            u32 sbase = stg_b[kt & 1];
            #pragma unroll
            for (int a = 0; a < 4; a++) {
                u32 dstb = sbase + a * ARRB;
                #pragma unroll
                for (int i = 0; i < 4; i++) {
                    int c = tid + i * 128;
                    int row = c >> 3, col = c & 7;
                    cpa16(dstb + SWX(row, col), srcs[a] + (size_t)row * HH + col * 8);
                }
            }
            CP_COMMIT();
            CP_WAIT1();
        } else {
            CP_WAIT0();
        }
        __syncthreads();

        const u32 khb = stg_b[(kt + 1) & 1];
        const u32 klb = khb + ARRB;
        const u32 vhb = khb + 2 * ARRB;
        const u32 vlb = khb + 3 * ARRB;

        // ---- S = Q K^T (3-term split; scores already in log2 units) ----
        float S[8][4];
        #pragma unroll
        for (int n = 0; n < 8; n++)
            #pragma unroll
            for (int j = 0; j < 4; j++) S[n][j] = 0.f;

        #pragma unroll
        for (int n = 0; n < 8; n++) {
            int brow = n * 8 + (l16 & 7);
            #pragma unroll
            for (int ks = 0; ks < 4; ks++) {
                int c = ks * 2 + (l16 >> 3);
                u32 boff = SWX(brow, c);
                u32 bh[2], bl[2];
                ldsm_x2(bh, khb + boff);
                ldsm_x2(bl, klb + boff);
                mma_bf16(S[n], qa_h[ks], bh);
                mma_bf16(S[n], qa_h[ks], bl);
                mma_bf16(S[n], qa_l[ks], bh);
            }
        }

        // ---- causal mask (diagonal tile only) ----
        if (kt == qt) {
            const int k0 = kt * 64;
            #pragma unroll
            for (int n = 0; n < 8; n++) {
                int colb = k0 + n * 8 + (lane & 3) * 2;
                #pragma unroll
                for (int j = 0; j < 4; j++) {
                    int col = colb + (j & 1);
                    int row = qrow0 + (j >> 1) * 8;
                    if (col > row) S[n][j] = -1e30f;
                }
            }
        }

        // ---- online softmax (base-2 domain, bare ex2) ----
        float fac[2];
        #pragma unroll
        for (int h = 0; h < 2; h++) {
            float mx = -1e30f;
            #pragma unroll
            for (int n = 0; n < 8; n++)
                mx = fmaxf(mx, fmaxf(S[n][h * 2], S[n][h * 2 + 1]));
            mx = fmaxf(mx, __shfl_xor_sync(0xffffffffu, mx, 1));
            mx = fmaxf(mx, __shfl_xor_sync(0xffffffffu, mx, 2));
            float mnew = fmaxf(mrow[h], mx);
            fac[h] = ex2(mrow[h] - mnew);
            mrow[h] = mnew;
            float sum = 0.f;
            #pragma unroll
            for (int n = 0; n < 8; n++) {
                float p0 = ex2(S[n][h * 2]     - mnew);
                float p1 = ex2(S[n][h * 2 + 1] - mnew);
                S[n][h * 2] = p0;
                S[n][h * 2 + 1] = p1;
                sum += p0 + p1;
            }
            sum += __shfl_xor_sync(0xffffffffu, sum, 1);
            sum += __shfl_xor_sync(0xffffffffu, sum, 2);
            lrow[h] = lrow[h] * fac[h] + sum;
            #pragma unroll
            for (int n = 0; n < 8; n++) {
                Oacc[n][h * 2]     *= fac[h];
                Oacc[n][h * 2 + 1] *= fac[h];
            }
        }

        // ---- O += P V (reg->reg pack of P; 3-term split) ----
        #pragma unroll
        for (int ks = 0; ks < 4; ks++) {
            u32 pa_h[4], pa_l[4];
            #pragma unroll
            for (int j = 0; j < 4; j++) {
                int n = 2 * ks + (j >> 1);
                int base = (j & 1) * 2;
                split2(S[n][base], S[n][base + 1], pa_h[j], pa_l[j]);
            }
            int vrow = ks * 16 + l16;
            #pragma unroll
            for (int n = 0; n < 8; n++) {
                u32 voff = SWX(vrow, n);
                u32 bh[2], bl[2];
                ldsm_x2t(bh, vhb + voff);
                ldsm_x2t(bl, vlb + voff);
                mma_bf16(Oacc[n], pa_h, bh);
                mma_bf16(Oacc[n], pa_h, bl);
                mma_bf16(Oacc[n], pa_l, bh);
            }
        }
        __syncthreads();   // all reads of this stage done before it is re-filled
    }

    // ---- finalize ----
    float inv0 = 1.f / lrow[0];
    float inv1 = 1.f / lrow[1];
    #pragma unroll
    for (int n = 0; n < 8; n++) {
        int col = n * 8 + (lane & 3) * 2;
        int row0 = q0 + wp * 16 + (lane >> 2);
        float2 v0 = make_float2(Oacc[n][0] * inv0, Oacc[n][1] * inv0);
        float2 v1 = make_float2(Oacc[n][2] * inv1, Oacc[n][3] * inv1);
        *reinterpret_cast<float2*>(out + ((size_t)b * TT + row0) * HH + col) = v0;
        *reinterpret_cast<float2*>(out + ((size_t)b * TT + row0 + 8) * HH + col) = v1;
    }
}

// ---------------------------------------------------------------------------
extern "C" void kernel_launch(void* const* d_in, const int* in_sizes, int n_in,
                              void* d_out, int out_size)
{
    const float* x  = (const float*)d_in[0];
    const float* Wk = (const float*)d_in[1];
    const float* Wq = (const float*)d_in[2];
    const float* Wv = (const float*)d_in[3];
    float* out = (float*)d_out;
    (void)in_sizes; (void)n_in; (void)out_size;

    split_w<<<(3 * HH * CCH) / 256, 256>>>(Wk, Wq, Wv);

    dim3 gridP(TT / 64, BB);
    proj_mma<<<gridP, 128>>>(x);

    static int attr_set = 0;
    if (!attr_set) {
        cudaFuncSetAttribute(attn_mma, cudaFuncAttributeMaxDynamicSharedMemorySize, ATTN_SMEM);
        attr_set = 1;
    }
    dim3 gridA(TT / 64, BB);
    attn_mma<<<gridA, 128, ATTN_SMEM>>>(out);
}